// round 15
// baseline (speedup 1.0000x reference)
#include <cuda_runtime.h>
#include <cuda_fp16.h>
#include <math.h>
#include <stdint.h>

// Problem dims (fixed)
#define BB 8
#define MM 2048
#define DD 1024
#define HALF_D 512
#define ROWS 16384           // BB*MM

// ---------------------------------------------------------------------------
// Device-global scratch (allocation-free, graph-capture safe). Plain fp16.
// ---------------------------------------------------------------------------
__device__ __half g_xh[(size_t)ROWS * DD];        // x fp16
__device__ __half g_wh[(size_t)(3 * DD) * DD];    // [wq;wk;wv] fp16
__device__ __half g_Qh[(size_t)ROWS * DD];        // rotated Q fp16
__device__ __half g_Kh[(size_t)ROWS * DD];        // rotated K fp16
__device__ __half g_VhT[(size_t)BB * DD * MM];    // V^T fp16 (from proj epilogue)
__device__ __half g_Eh[(size_t)BB * MM * MM];     // exp(scores) fp16
__device__ float g_psum[(size_t)ROWS * 32];       // per-row exp partial sums
__device__ float2 g_cs[(size_t)MM * HALF_D];      // interleaved {cos, sin}

// ---------------------------------------------------------------------------
// PTX helpers (base-ISA: mma.sync / ldmatrix / cp.async)
// ---------------------------------------------------------------------------
__device__ __forceinline__ uint32_t smem_u32(const void* p) {
    uint32_t a;
    asm("{ .reg .u64 t; cvta.to.shared.u64 t, %1; cvt.u32.u64 %0, t; }" : "=r"(a) : "l"(p));
    return a;
}
__device__ __forceinline__ void mma16816(float* d, const uint32_t* a, const uint32_t* b) {
    asm volatile(
        "mma.sync.aligned.m16n8k16.row.col.f32.f16.f16.f32 "
        "{%0,%1,%2,%3}, {%4,%5,%6,%7}, {%8,%9}, {%0,%1,%2,%3};"
        : "+f"(d[0]), "+f"(d[1]), "+f"(d[2]), "+f"(d[3])
        : "r"(a[0]), "r"(a[1]), "r"(a[2]), "r"(a[3]), "r"(b[0]), "r"(b[1]));
}
__device__ __forceinline__ void ldsm4(uint32_t* r, uint32_t addr) {
    asm volatile("ldmatrix.sync.aligned.m8n8.x4.shared.b16 {%0,%1,%2,%3}, [%4];"
                 : "=r"(r[0]), "=r"(r[1]), "=r"(r[2]), "=r"(r[3]) : "r"(addr));
}
__device__ __forceinline__ void cpasync16(uint32_t dst, const void* src) {
    asm volatile("cp.async.cg.shared.global [%0], [%1], 16;" :: "r"(dst), "l"(src));
}
__device__ __forceinline__ void cp_commit() {
    asm volatile("cp.async.commit_group;" ::: "memory");
}
template <int N>
__device__ __forceinline__ void cp_wait() {
    asm volatile("cp.async.wait_group %0;" :: "n"(N) : "memory");
}

// ---------------------------------------------------------------------------
// Prep kernel: RoPE tables + x->fp16 + weights->fp16, one launch.
// ---------------------------------------------------------------------------
__global__ void prep_kernel(const float* __restrict__ x,
                            const float* __restrict__ wq,
                            const float* __restrict__ wk,
                            const float* __restrict__ wv) {
    int b = blockIdx.x;
    int t = threadIdx.x;
    if (b < 4096) {
        int idx = b * 256 + t;
        int m = idx / HALF_D;
        int i = idx % HALF_D;
        double theta_d = pow(10000.0, -2.0 * ((double)i - 1.0) / (double)DD);
        float ang = (float)m * (float)theta_d;
        g_cs[idx] = make_float2(cosf(ang), sinf(ang));
    } else if (b < 20480) {
        long idx = ((long)(b - 4096) * 256 + t) * 4;
        float4 v = *reinterpret_cast<const float4*>(x + idx);
        *reinterpret_cast<__half2*>(g_xh + idx)     = __floats2half2_rn(v.x, v.y);
        *reinterpret_cast<__half2*>(g_xh + idx + 2) = __floats2half2_rn(v.z, v.w);
    } else {
        int j = b - 20480;
        int w = j >> 10;
        long idx = ((long)(j & 1023) * 256 + t) * 4;
        const float* src = w == 0 ? wq : (w == 1 ? wk : wv);
        float4 v = *reinterpret_cast<const float4*>(src + idx);
        __half* r = g_wh + (long)w * DD * DD + idx;
        *reinterpret_cast<__half2*>(r)     = __floats2half2_rn(v.x, v.y);
        *reinterpret_cast<__half2*>(r + 2) = __floats2half2_rn(v.z, v.w);
    }
}

// ---------------------------------------------------------------------------
// Persistent mma.sync fp16 GEMM, 256x128 CTA tiles, 256 threads, 1 CTA/SM.
// 8 warps (4M x 2N), per-warp 64x64 tile (identical mainloop as before).
// BK=64, 2-stage cp.async pipeline continuous across tiles.
//   EPI=1: merged QKV projection (RoPE Q/K, transpose V)
//   EPI=2: scores: exp(alpha*s) -> g_Eh + psum
//   EPI=3: PV: scale by 1/rowsum -> fp32 out (two 64-col halves)
// ---------------------------------------------------------------------------
#define TILE_A_B (256 * 64 * 2)            // 32 KB A stage
#define STAGEB   (TILE_A_B + 128 * 64 * 2) // 48 KB per stage (A+B)
#define EPIOFF   (2 * STAGEB)              // 96 KB
#define GSMEM    (EPIOFF + 69632 + 1536)   // + epi staging + s_inv pad

template <int EPI>
__global__ void __launch_bounds__(256, 1) mma_gemm_kernel(
    const __half* __restrict__ A, const __half* __restrict__ B,
    float* __restrict__ C, int K, int ldc, long sA, long sB, long sC, float alpha,
    int tX, int tXY, int ntiles)
{
    constexpr int NT = 8;
    constexpr int RS = 136;                // epi staging stride (halfs)

    extern __shared__ char smem[];
    const uint32_t sb = smem_u32(smem);
    const int tid = threadIdx.x;
    const int wid = tid >> 5, lane = tid & 31;
    const int wm = wid & 3;                // 4 M warps (x64 rows -> 256)
    const int wn = wid >> 2;               // 2 N warps (x64 cols -> 128)
    const int ldRow = tid >> 3;            // 0..31
    const int ldC = tid & 7;
    const int lrow = lane & 15;
    const int lcol = lane >> 4;
    const int g = lane >> 2, tg = lane & 3;
    const int nch = K >> 6;

    auto bases = [&](int t, const __half*& Ab, const __half*& Bb) {
        int bz = t / tXY;
        int rem = t - bz * tXY;
        int by = rem / tX;
        int bx = rem - by * tX;
        Ab = A + bz * sA + (long)by * 256 * K;
        Bb = B + bz * sB + (long)bx * 128 * K;
    };

    auto issue = [&](const __half* Ab, const __half* Bb, int ch, int buf) {
        const int kk = ch << 6;
        const uint32_t sbA = sb + buf * STAGEB;
        const uint32_t sbB = sbA + TILE_A_B;
#pragma unroll
        for (int i = 0; i < 8; i++) {
            int row = ldRow + i * 32;
            uint32_t off = ((uint32_t)row * 8u + (uint32_t)(ldC ^ (row & 7))) * 16u;
            cpasync16(sbA + off, Ab + (long)row * K + kk + ldC * 8);
        }
#pragma unroll
        for (int i = 0; i < 4; i++) {
            int row = ldRow + i * 32;
            uint32_t off = ((uint32_t)row * 8u + (uint32_t)(ldC ^ (row & 7))) * 16u;
            cpasync16(sbB + off, Bb + (long)row * K + kk + ldC * 8);
        }
        cp_commit();
    };

    const __half *curA = nullptr, *curB = nullptr, *nxtA = nullptr, *nxtB = nullptr;
    if (blockIdx.x < (unsigned)ntiles) {
        bases(blockIdx.x, curA, curB);
        issue(curA, curB, 0, 0);
        issue(curA, curB, 1, 1);
    }

    for (int tidx = blockIdx.x; tidx < ntiles; tidx += gridDim.x) {
        const int bz = tidx / tXY;
        const int rem = tidx - bz * tXY;
        const int by = rem / tX;
        const int bx = rem - by * tX;
        const long row0 = (long)by * 256;
        const long col0 = (long)bx * 128;
        float* Cbase = C + bz * sC;

        const int nt2 = tidx + gridDim.x;
        const bool hasNext = nt2 < ntiles;
        if (hasNext) bases(nt2, nxtA, nxtB);

        float acc[4][NT][4];
#pragma unroll
        for (int i = 0; i < 4; i++)
#pragma unroll
            for (int j = 0; j < NT; j++)
#pragma unroll
                for (int q = 0; q < 4; q++) acc[i][j][q] = 0.0f;

        for (int ch = 0; ch < nch; ch++) {
            if (!hasNext && ch == nch - 1) cp_wait<0>(); else cp_wait<1>();
            __syncthreads();

            const uint32_t sbA = sb + (ch & 1) * STAGEB;
            const uint32_t sbB = sbA + TILE_A_B;

            uint32_t fa[2][4][4];
            uint32_t fb[2][NT][2];

            auto load_frags = [&](int ks, int pb) {
#pragma unroll
                for (int mt = 0; mt < 4; mt++) {
                    int row = wm * 64 + mt * 16 + lrow;
                    int c = 2 * ks + lcol;
                    uint32_t addr = sbA + ((uint32_t)row * 8u + (uint32_t)(c ^ (row & 7))) * 16u;
                    ldsm4(fa[pb][mt], addr);
                }
#pragma unroll
                for (int p = 0; p < NT / 2; p++) {
                    int row = wn * 64 + p * 16 + lrow;
                    int c = 2 * ks + lcol;
                    uint32_t addr = sbB + ((uint32_t)row * 8u + (uint32_t)(c ^ (row & 7))) * 16u;
                    uint32_t r[4];
                    ldsm4(r, addr);
                    fb[pb][2 * p][0] = r[0]; fb[pb][2 * p][1] = r[2];
                    fb[pb][2 * p + 1][0] = r[1]; fb[pb][2 * p + 1][1] = r[3];
                }
            };

            load_frags(0, 0);
#pragma unroll
            for (int ks = 0; ks < 4; ks++) {
                if (ks < 3) load_frags(ks + 1, (ks + 1) & 1);
#pragma unroll
                for (int mt = 0; mt < 4; mt++)
#pragma unroll
                    for (int nt = 0; nt < NT; nt++)
                        mma16816(acc[mt][nt], fa[ks & 1][mt], fb[ks & 1][nt]);
            }
            __syncthreads();

            // continuous cross-tile prefetch
            int j = ch + 2;
            if (j < nch) issue(curA, curB, j, j & 1);
            else if (hasNext && j - nch < 2) issue(nxtA, nxtB, j - nch, j & 1);
        }

        // ---- epilogue (dedicated staging region; overlaps next-tile loads) --
        if (EPI == 1) {
            __half* sv = reinterpret_cast<__half*>(smem + EPIOFF);
            if (col0 < 2048) {
                const int k0 = (int)col0 & 1023;
#pragma unroll
                for (int mt = 0; mt < 4; mt++) {
                    int rl = wm * 64 + mt * 16 + g;
#pragma unroll
                    for (int nt = 0; nt < NT; nt++) {
                        int cl = wn * 64 + nt * 8 + tg * 2;
                        int pidx = (k0 + cl) >> 1;
#pragma unroll
                        for (int h = 0; h < 2; h++) {
                            int m = (int)((row0 + rl + h * 8) & (MM - 1));
                            float2 cs = g_cs[(size_t)m * HALF_D + pidx];
                            float e = acc[mt][nt][2 * h], o = acc[mt][nt][2 * h + 1];
                            float re = e * cs.x + o * cs.y;
                            float ro = -e * cs.y + o * cs.x;
                            *reinterpret_cast<__half2*>(&sv[(rl + h * 8) * RS + cl]) =
                                __floats2half2_rn(re, ro);
                        }
                    }
                }
                __syncthreads();
                __half* base = (col0 < 1024 ? g_Qh : g_Kh);
#pragma unroll
                for (int it = 0; it < 16; it++) {
                    int row = it * 16 + (tid >> 4);
                    int cc = (tid & 15) * 8;
                    *reinterpret_cast<uint4*>(base + (row0 + row) * (long)DD + k0 + cc) =
                        *reinterpret_cast<uint4*>(&sv[row * RS + cc]);
                }
            } else {
#pragma unroll
                for (int mt = 0; mt < 4; mt++)
#pragma unroll
                    for (int nt = 0; nt < NT; nt++) {
                        int cl = wn * 64 + nt * 8 + tg * 2;
#pragma unroll
                        for (int h = 0; h < 2; h++) {
                            int rl = wm * 64 + mt * 16 + g + h * 8;
                            *reinterpret_cast<__half2*>(&sv[rl * RS + cl]) =
                                __floats2half2_rn(acc[mt][nt][2 * h], acc[mt][nt][2 * h + 1]);
                        }
                    }
                __syncthreads();
                int b = (int)(row0 >> 11);
                int m0 = (int)(row0 & (MM - 1));
                int vcol = (int)col0 - 2048 + (tid & 127);
                int mh = tid >> 7;                  // 0/1: which 128-row half
                __half* dst = g_VhT + ((long)(b * DD + vcol)) * MM + m0 + mh * 128;
#pragma unroll
                for (int c8 = 0; c8 < 16; c8++) {
                    __half tmp[8];
#pragma unroll
                    for (int jj = 0; jj < 8; jj++)
                        tmp[jj] = sv[(mh * 128 + c8 * 8 + jj) * RS + (tid & 127)];
                    *reinterpret_cast<uint4*>(dst + c8 * 8) = *reinterpret_cast<uint4*>(tmp);
                }
            }
        } else if (EPI == 2) {
            __half* sv = reinterpret_cast<__half*>(smem + EPIOFF);
            float rs[4][2];
#pragma unroll
            for (int mt = 0; mt < 4; mt++) { rs[mt][0] = 0.0f; rs[mt][1] = 0.0f; }
#pragma unroll
            for (int mt = 0; mt < 4; mt++) {
                int rl = wm * 64 + mt * 16 + g;
#pragma unroll
                for (int nt = 0; nt < NT; nt++) {
                    int cl = wn * 64 + nt * 8 + tg * 2;
#pragma unroll
                    for (int h = 0; h < 2; h++) {
                        float e0 = expf(alpha * acc[mt][nt][2 * h]);
                        float e1 = expf(alpha * acc[mt][nt][2 * h + 1]);
                        *reinterpret_cast<__half2*>(&sv[(rl + h * 8) * RS + cl]) =
                            __floats2half2_rn(e0, e1);
                        rs[mt][h] += e0 + e1;
                    }
                }
            }
#pragma unroll
            for (int mt = 0; mt < 4; mt++)
#pragma unroll
                for (int h = 0; h < 2; h++) {
                    float v = rs[mt][h];
                    v += __shfl_xor_sync(0xffffffffu, v, 1);
                    v += __shfl_xor_sync(0xffffffffu, v, 2);
                    rs[mt][h] = v;
                }
            if (tg == 0) {
#pragma unroll
                for (int mt = 0; mt < 4; mt++)
#pragma unroll
                    for (int h = 0; h < 2; h++) {
                        long rr = row0 + wm * 64 + mt * 16 + g + h * 8;
                        g_psum[((long)bz * MM + rr) * 32 + bx * 2 + wn] = rs[mt][h];
                    }
            }
            __syncthreads();
            __half* Eb = g_Eh + (long)bz * MM * MM;
#pragma unroll
            for (int it = 0; it < 16; it++) {
                int row = it * 16 + (tid >> 4);
                int cc = (tid & 15) * 8;
                *reinterpret_cast<uint4*>(Eb + (row0 + row) * MM + col0 + cc) =
                    *reinterpret_cast<uint4*>(&sv[row * RS + cc]);
            }
        } else {
            // EPI == 3: PV — divide by row sums, two 64-col halves
            constexpr int RSF = 68;
            float* svf = reinterpret_cast<float*>(smem + EPIOFF);
            float* s_inv = reinterpret_cast<float*>(smem + EPIOFF + 256 * RSF * 4);
            {
                const float4* pp = reinterpret_cast<const float4*>(
                    g_psum + ((long)bz * MM + row0 + tid) * 32);
                float s = 0.0f;
#pragma unroll
                for (int q = 0; q < 8; q++) {
                    float4 v = pp[q];
                    s += (v.x + v.y) + (v.z + v.w);
                }
                s_inv[tid] = 1.0f / s;
            }
            __syncthreads();
#pragma unroll
            for (int hh = 0; hh < 2; hh++) {
                if (wn == hh) {
#pragma unroll
                    for (int mt = 0; mt < 4; mt++) {
                        int l0 = wm * 64 + mt * 16 + g;
                        float inv0 = s_inv[l0];
                        float inv1 = s_inv[l0 + 8];
#pragma unroll
                        for (int nt = 0; nt < NT; nt++) {
                            int cl = nt * 8 + tg * 2;
                            *reinterpret_cast<float2*>(&svf[l0 * RSF + cl]) =
                                make_float2(acc[mt][nt][0] * inv0, acc[mt][nt][1] * inv0);
                            *reinterpret_cast<float2*>(&svf[(l0 + 8) * RSF + cl]) =
                                make_float2(acc[mt][nt][2] * inv1, acc[mt][nt][3] * inv1);
                        }
                    }
                }
                __syncthreads();
#pragma unroll
                for (int it = 0; it < 16; it++) {
                    int row = it * 16 + (tid >> 4);
                    int cc = (tid & 15) * 4;
                    *reinterpret_cast<uint4*>(Cbase + (row0 + row) * ldc + col0 + hh * 64 + cc) =
                        *reinterpret_cast<uint4*>(&svf[row * RSF + cc]);
                }
                __syncthreads();
            }
        }

        curA = nxtA;
        curB = nxtB;
    }
}

// ---------------------------------------------------------------------------
// Launch. 4 kernels: prep, proj, scores, PV. 148 persistent CTAs each.
// ---------------------------------------------------------------------------
extern "C" void kernel_launch(void* const* d_in, const int* in_sizes, int n_in,
                              void* d_out, int out_size) {
    (void)in_sizes; (void)n_in; (void)out_size;
    const float* x  = (const float*)d_in[0];
    const float* wq = (const float*)d_in[1];
    const float* wk = (const float*)d_in[2];
    const float* wv = (const float*)d_in[3];
    float* out = (float*)d_out;

    __half *xh, *wh, *Qh, *Kh, *VhT, *Eh;
    cudaGetSymbolAddress((void**)&xh, g_xh);
    cudaGetSymbolAddress((void**)&wh, g_wh);
    cudaGetSymbolAddress((void**)&Qh, g_Qh);
    cudaGetSymbolAddress((void**)&Kh, g_Kh);
    cudaGetSymbolAddress((void**)&VhT, g_VhT);
    cudaGetSymbolAddress((void**)&Eh, g_Eh);

    cudaFuncSetAttribute(mma_gemm_kernel<1>, cudaFuncAttributeMaxDynamicSharedMemorySize, GSMEM);
    cudaFuncSetAttribute(mma_gemm_kernel<2>, cudaFuncAttributeMaxDynamicSharedMemorySize, GSMEM);
    cudaFuncSetAttribute(mma_gemm_kernel<3>, cudaFuncAttributeMaxDynamicSharedMemorySize, GSMEM);

    // 0: prep (tables + cvt_x + cvt_w)
    prep_kernel<<<23552, 256>>>(x, wq, wk, wv);

    // 1: Merged QKV projection (256-row tiles: 64 x 24 = 1536 tiles, K=1024)
    mma_gemm_kernel<1><<<148, 256, GSMEM>>>(xh, wh, nullptr, DD, 0,
                                            0, 0, 0, 1.0f,
                                            24, 24 * 64, 1536);

    // 2: scores -> exp fp16 + psum (8 x 16 x 8 = 1024 tiles, K=1024)
    mma_gemm_kernel<2><<<148, 256, GSMEM>>>(Qh, Kh, nullptr, DD, 0,
                                            (long)MM * DD, (long)MM * DD, 0,
                                            0.03125f,
                                            16, 16 * 8, 1024);

    // 3: out = exp(S) @ V / rowsum (8 x 8 x 8 = 512 tiles, K=2048)
    mma_gemm_kernel<3><<<148, 256, GSMEM>>>(Eh, VhT, out, MM, DD,
                                            (long)MM * MM, (long)DD * MM,
                                            (long)MM * DD, 1.0f,
                                            8, 8 * 8, 512);
}

// round 16
// speedup vs baseline: 1.1093x; 1.1093x over previous
#include <cuda_runtime.h>
#include <cuda_fp16.h>
#include <math.h>
#include <stdint.h>

// Problem dims (fixed)
#define BB 8
#define MM 2048
#define DD 1024
#define HALF_D 512
#define ROWS 16384           // BB*MM

// ---------------------------------------------------------------------------
// Device-global scratch (allocation-free, graph-capture safe). Plain fp16.
// ---------------------------------------------------------------------------
__device__ __half g_xh[(size_t)ROWS * DD];        // x fp16
__device__ __half g_wh[(size_t)(3 * DD) * DD];    // [wq;wk;wv] fp16
__device__ __half g_Qh[(size_t)ROWS * DD];        // rotated Q fp16
__device__ __half g_Kh[(size_t)ROWS * DD];        // rotated K fp16
__device__ __half g_VhT[(size_t)BB * DD * MM];    // V^T fp16 (from proj epilogue)
__device__ __half g_Eh[(size_t)BB * MM * MM];     // exp(scores) fp16
__device__ float g_psum[(size_t)ROWS * 32];       // per-row exp partial sums
__device__ float2 g_cs[(size_t)MM * HALF_D];      // interleaved {cos, sin}

// ---------------------------------------------------------------------------
// PTX helpers (base-ISA: mma.sync / ldmatrix / cp.async)
// ---------------------------------------------------------------------------
__device__ __forceinline__ uint32_t smem_u32(const void* p) {
    uint32_t a;
    asm("{ .reg .u64 t; cvta.to.shared.u64 t, %1; cvt.u32.u64 %0, t; }" : "=r"(a) : "l"(p));
    return a;
}
__device__ __forceinline__ void mma16816(float* d, const uint32_t* a, const uint32_t* b) {
    asm volatile(
        "mma.sync.aligned.m16n8k16.row.col.f32.f16.f16.f32 "
        "{%0,%1,%2,%3}, {%4,%5,%6,%7}, {%8,%9}, {%0,%1,%2,%3};"
        : "+f"(d[0]), "+f"(d[1]), "+f"(d[2]), "+f"(d[3])
        : "r"(a[0]), "r"(a[1]), "r"(a[2]), "r"(a[3]), "r"(b[0]), "r"(b[1]));
}
__device__ __forceinline__ void ldsm4(uint32_t* r, uint32_t addr) {
    asm volatile("ldmatrix.sync.aligned.m8n8.x4.shared.b16 {%0,%1,%2,%3}, [%4];"
                 : "=r"(r[0]), "=r"(r[1]), "=r"(r[2]), "=r"(r[3]) : "r"(addr));
}
__device__ __forceinline__ void cpasync16(uint32_t dst, const void* src) {
    asm volatile("cp.async.cg.shared.global [%0], [%1], 16;" :: "r"(dst), "l"(src));
}
__device__ __forceinline__ void cp_commit() {
    asm volatile("cp.async.commit_group;" ::: "memory");
}
template <int N>
__device__ __forceinline__ void cp_wait() {
    asm volatile("cp.async.wait_group %0;" :: "n"(N) : "memory");
}

// ---------------------------------------------------------------------------
// Prep kernel: RoPE tables + x->fp16 + weights->fp16, one launch.
// ---------------------------------------------------------------------------
__global__ void prep_kernel(const float* __restrict__ x,
                            const float* __restrict__ wq,
                            const float* __restrict__ wk,
                            const float* __restrict__ wv) {
    int b = blockIdx.x;
    int t = threadIdx.x;
    if (b < 4096) {
        int idx = b * 256 + t;
        int m = idx / HALF_D;
        int i = idx % HALF_D;
        double theta_d = pow(10000.0, -2.0 * ((double)i - 1.0) / (double)DD);
        float ang = (float)m * (float)theta_d;
        g_cs[idx] = make_float2(cosf(ang), sinf(ang));
    } else if (b < 20480) {
        long idx = ((long)(b - 4096) * 256 + t) * 4;
        float4 v = *reinterpret_cast<const float4*>(x + idx);
        *reinterpret_cast<__half2*>(g_xh + idx)     = __floats2half2_rn(v.x, v.y);
        *reinterpret_cast<__half2*>(g_xh + idx + 2) = __floats2half2_rn(v.z, v.w);
    } else {
        int j = b - 20480;
        int w = j >> 10;
        long idx = ((long)(j & 1023) * 256 + t) * 4;
        const float* src = w == 0 ? wq : (w == 1 ? wk : wv);
        float4 v = *reinterpret_cast<const float4*>(src + idx);
        __half* r = g_wh + (long)w * DD * DD + idx;
        *reinterpret_cast<__half2*>(r)     = __floats2half2_rn(v.x, v.y);
        *reinterpret_cast<__half2*>(r + 2) = __floats2half2_rn(v.z, v.w);
    }
}

// ---------------------------------------------------------------------------
// Persistent mma.sync fp16 GEMM, 128x128 CTA tiles, BK=64, 2-stage cp.async
// pipeline made CONTINUOUS across tiles (chunks of tile t+1 prefetch during
// the last chunks of tile t; epilogue overlaps those loads). Dedicated smem
// staging region for all epilogues (coalesced 16B stores). 2 CTAs/SM.
//   EPI=1: merged QKV projection (RoPE Q/K, transpose V)
//   EPI=2: scores: __expf(alpha*s) -> g_Eh + psum
//   EPI=3: PV: scale by 1/rowsum -> fp32 out (two 64-col halves)
// ---------------------------------------------------------------------------
#define STAGEB 32768                       // one pipeline stage (A+B), bytes
#define EPIOFF (2 * STAGEB)                // staging region offset
#define GSMEM  (EPIOFF + 34816 + 512)      // total dynamic smem

template <int EPI>
__global__ void __launch_bounds__(128, 2) mma_gemm_kernel(
    const __half* __restrict__ A, const __half* __restrict__ B,
    float* __restrict__ C, int K, int ldc, long sA, long sB, long sC, float alpha,
    int tX, int tXY, int ntiles)
{
    constexpr int NT = 8;
    constexpr int TILE_A = 128 * 64 * 2;   // 16 KB
    constexpr int RS = 136;                // epi staging stride (halfs)

    extern __shared__ char smem[];
    const uint32_t sb = smem_u32(smem);
    const int tid = threadIdx.x;
    const int wid = tid >> 5, lane = tid & 31;
    const int wm = wid & 1;
    const int wn = wid >> 1;
    const int ldRow = tid >> 3;
    const int ldC = tid & 7;
    const int lrow = lane & 15;
    const int lcol = lane >> 4;
    const int g = lane >> 2, tg = lane & 3;
    const int nch = K >> 6;

    auto bases = [&](int t, const __half*& Ab, const __half*& Bb) {
        int bz = t / tXY;
        int rem = t - bz * tXY;
        int by = rem / tX;
        int bx = rem - by * tX;
        Ab = A + bz * sA + (long)by * 128 * K;
        Bb = B + bz * sB + (long)bx * 128 * K;
    };

    auto issue = [&](const __half* Ab, const __half* Bb, int ch, int buf) {
        const int kk = ch << 6;
        const uint32_t sbA = sb + buf * STAGEB;
        const uint32_t sbB = sbA + TILE_A;
#pragma unroll
        for (int i = 0; i < 8; i++) {
            int row = ldRow + i * 16;
            uint32_t off = ((uint32_t)row * 8u + (uint32_t)(ldC ^ (row & 7))) * 16u;
            cpasync16(sbA + off, Ab + (long)row * K + kk + ldC * 8);
            cpasync16(sbB + off, Bb + (long)row * K + kk + ldC * 8);
        }
        cp_commit();
    };

    const __half *curA = nullptr, *curB = nullptr, *nxtA = nullptr, *nxtB = nullptr;
    if (blockIdx.x < (unsigned)ntiles) {
        bases(blockIdx.x, curA, curB);
        issue(curA, curB, 0, 0);
        issue(curA, curB, 1, 1);
    }

    for (int tidx = blockIdx.x; tidx < ntiles; tidx += gridDim.x) {
        const int bz = tidx / tXY;
        const int rem = tidx - bz * tXY;
        const int by = rem / tX;
        const int bx = rem - by * tX;
        const long row0 = (long)by * 128;
        const long col0 = (long)bx * 128;
        float* Cbase = C + bz * sC;

        const int nt2 = tidx + gridDim.x;
        const bool hasNext = nt2 < ntiles;
        if (hasNext) bases(nt2, nxtA, nxtB);

        float acc[4][NT][4];
#pragma unroll
        for (int i = 0; i < 4; i++)
#pragma unroll
            for (int j = 0; j < NT; j++)
#pragma unroll
                for (int q = 0; q < 4; q++) acc[i][j][q] = 0.0f;

        for (int ch = 0; ch < nch; ch++) {
            if (!hasNext && ch == nch - 1) cp_wait<0>(); else cp_wait<1>();
            __syncthreads();

            const uint32_t sbA = sb + (ch & 1) * STAGEB;
            const uint32_t sbB = sbA + TILE_A;

            uint32_t fa[2][4][4];
            uint32_t fb[2][NT][2];

            auto load_frags = [&](int ks, int pb) {
#pragma unroll
                for (int mt = 0; mt < 4; mt++) {
                    int row = wm * 64 + mt * 16 + lrow;
                    int c = 2 * ks + lcol;
                    uint32_t addr = sbA + ((uint32_t)row * 8u + (uint32_t)(c ^ (row & 7))) * 16u;
                    ldsm4(fa[pb][mt], addr);
                }
#pragma unroll
                for (int p = 0; p < NT / 2; p++) {
                    int row = wn * 64 + p * 16 + lrow;
                    int c = 2 * ks + lcol;
                    uint32_t addr = sbB + ((uint32_t)row * 8u + (uint32_t)(c ^ (row & 7))) * 16u;
                    uint32_t r[4];
                    ldsm4(r, addr);
                    fb[pb][2 * p][0] = r[0]; fb[pb][2 * p][1] = r[2];
                    fb[pb][2 * p + 1][0] = r[1]; fb[pb][2 * p + 1][1] = r[3];
                }
            };

            load_frags(0, 0);
#pragma unroll
            for (int ks = 0; ks < 4; ks++) {
                if (ks < 3) load_frags(ks + 1, (ks + 1) & 1);
#pragma unroll
                for (int mt = 0; mt < 4; mt++)
#pragma unroll
                    for (int nt = 0; nt < NT; nt++)
                        mma16816(acc[mt][nt], fa[ks & 1][mt], fb[ks & 1][nt]);
            }
            __syncthreads();

            // continuous cross-tile prefetch
            int j = ch + 2;
            if (j < nch) issue(curA, curB, j, j & 1);
            else if (hasNext && j - nch < 2) issue(nxtA, nxtB, j - nch, j & 1);
        }

        // ---- epilogue (dedicated staging region; overlaps next-tile loads) --
        if (EPI == 1) {
            __half* sv = reinterpret_cast<__half*>(smem + EPIOFF);
            if (col0 < 2048) {
                const int k0 = (int)col0 & 1023;
#pragma unroll
                for (int mt = 0; mt < 4; mt++) {
                    int rl = wm * 64 + mt * 16 + g;
#pragma unroll
                    for (int nt = 0; nt < NT; nt++) {
                        int cl = wn * 64 + nt * 8 + tg * 2;
                        int pidx = (k0 + cl) >> 1;
#pragma unroll
                        for (int h = 0; h < 2; h++) {
                            int m = (int)((row0 + rl + h * 8) & (MM - 1));
                            float2 cs = g_cs[(size_t)m * HALF_D + pidx];
                            float e = acc[mt][nt][2 * h], o = acc[mt][nt][2 * h + 1];
                            float re = e * cs.x + o * cs.y;
                            float ro = -e * cs.y + o * cs.x;
                            *reinterpret_cast<__half2*>(&sv[(rl + h * 8) * RS + cl]) =
                                __floats2half2_rn(re, ro);
                        }
                    }
                }
                __syncthreads();
                __half* base = (col0 < 1024 ? g_Qh : g_Kh);
#pragma unroll
                for (int it = 0; it < 16; it++) {
                    int row = it * 8 + wid * 2 + (lane >> 4);
                    int cc = (lane & 15) * 8;
                    *reinterpret_cast<uint4*>(base + (row0 + row) * (long)DD + k0 + cc) =
                        *reinterpret_cast<uint4*>(&sv[row * RS + cc]);
                }
            } else {
#pragma unroll
                for (int mt = 0; mt < 4; mt++)
#pragma unroll
                    for (int nt = 0; nt < NT; nt++) {
                        int cl = wn * 64 + nt * 8 + tg * 2;
#pragma unroll
                        for (int h = 0; h < 2; h++) {
                            int rl = wm * 64 + mt * 16 + g + h * 8;
                            *reinterpret_cast<__half2*>(&sv[rl * RS + cl]) =
                                __floats2half2_rn(acc[mt][nt][2 * h], acc[mt][nt][2 * h + 1]);
                        }
                    }
                __syncthreads();
                int b = (int)(row0 >> 11);
                int m0 = (int)(row0 & (MM - 1));
                int vcol = (int)col0 - 2048 + tid;
                __half* dst = g_VhT + ((long)(b * DD + vcol)) * MM + m0;
#pragma unroll
                for (int c8 = 0; c8 < 16; c8++) {
                    __half tmp[8];
#pragma unroll
                    for (int jj = 0; jj < 8; jj++) tmp[jj] = sv[(c8 * 8 + jj) * RS + tid];
                    *reinterpret_cast<uint4*>(dst + c8 * 8) = *reinterpret_cast<uint4*>(tmp);
                }
            }
        } else if (EPI == 2) {
            __half* sv = reinterpret_cast<__half*>(smem + EPIOFF);
            float rs[4][2];
#pragma unroll
            for (int mt = 0; mt < 4; mt++) { rs[mt][0] = 0.0f; rs[mt][1] = 0.0f; }
#pragma unroll
            for (int mt = 0; mt < 4; mt++) {
                int rl = wm * 64 + mt * 16 + g;
#pragma unroll
                for (int nt = 0; nt < NT; nt++) {
                    int cl = wn * 64 + nt * 8 + tg * 2;
#pragma unroll
                    for (int h = 0; h < 2; h++) {
                        float e0 = __expf(alpha * acc[mt][nt][2 * h]);
                        float e1 = __expf(alpha * acc[mt][nt][2 * h + 1]);
                        *reinterpret_cast<__half2*>(&sv[(rl + h * 8) * RS + cl]) =
                            __floats2half2_rn(e0, e1);
                        rs[mt][h] += e0 + e1;
                    }
                }
            }
#pragma unroll
            for (int mt = 0; mt < 4; mt++)
#pragma unroll
                for (int h = 0; h < 2; h++) {
                    float v = rs[mt][h];
                    v += __shfl_xor_sync(0xffffffffu, v, 1);
                    v += __shfl_xor_sync(0xffffffffu, v, 2);
                    rs[mt][h] = v;
                }
            if (tg == 0) {
#pragma unroll
                for (int mt = 0; mt < 4; mt++)
#pragma unroll
                    for (int h = 0; h < 2; h++) {
                        long rr = row0 + wm * 64 + mt * 16 + g + h * 8;
                        g_psum[((long)bz * MM + rr) * 32 + bx * 2 + wn] = rs[mt][h];
                    }
            }
            __syncthreads();
            __half* Eb = g_Eh + (long)bz * MM * MM;
#pragma unroll
            for (int it = 0; it < 16; it++) {
                int row = it * 8 + wid * 2 + (lane >> 4);
                int cc = (lane & 15) * 8;
                *reinterpret_cast<uint4*>(Eb + (row0 + row) * MM + col0 + cc) =
                    *reinterpret_cast<uint4*>(&sv[row * RS + cc]);
            }
        } else {
            // EPI == 3: PV — divide by row sums, two 64-col halves
            constexpr int RSF = 68;
            float* svf = reinterpret_cast<float*>(smem + EPIOFF);
            float* s_inv = reinterpret_cast<float*>(smem + EPIOFF + 128 * RSF * 4);
            {
                const float4* pp = reinterpret_cast<const float4*>(
                    g_psum + ((long)bz * MM + row0 + tid) * 32);
                float s = 0.0f;
#pragma unroll
                for (int q = 0; q < 8; q++) {
                    float4 v = pp[q];
                    s += (v.x + v.y) + (v.z + v.w);
                }
                s_inv[tid] = 1.0f / s;
            }
            __syncthreads();
#pragma unroll
            for (int hh = 0; hh < 2; hh++) {
                if (wn == hh) {
#pragma unroll
                    for (int mt = 0; mt < 4; mt++) {
                        int l0 = wm * 64 + mt * 16 + g;
                        float inv0 = s_inv[l0];
                        float inv1 = s_inv[l0 + 8];
#pragma unroll
                        for (int nt = 0; nt < NT; nt++) {
                            int cl = nt * 8 + tg * 2;
                            *reinterpret_cast<float2*>(&svf[l0 * RSF + cl]) =
                                make_float2(acc[mt][nt][0] * inv0, acc[mt][nt][1] * inv0);
                            *reinterpret_cast<float2*>(&svf[(l0 + 8) * RSF + cl]) =
                                make_float2(acc[mt][nt][2] * inv1, acc[mt][nt][3] * inv1);
                        }
                    }
                }
                __syncthreads();
#pragma unroll
                for (int it = 0; it < 16; it++) {
                    int row = it * 8 + wid * 2 + (lane >> 4);
                    int cc = (lane & 15) * 4;
                    *reinterpret_cast<uint4*>(Cbase + (row0 + row) * ldc + col0 + hh * 64 + cc) =
                        *reinterpret_cast<uint4*>(&svf[row * RSF + cc]);
                }
                __syncthreads();
            }
        }

        curA = nxtA;
        curB = nxtB;
    }
}

// ---------------------------------------------------------------------------
// Launch. 4 kernels: prep, proj, scores, PV. Persistent grids.
// ---------------------------------------------------------------------------
extern "C" void kernel_launch(void* const* d_in, const int* in_sizes, int n_in,
                              void* d_out, int out_size) {
    (void)in_sizes; (void)n_in; (void)out_size;
    const float* x  = (const float*)d_in[0];
    const float* wq = (const float*)d_in[1];
    const float* wk = (const float*)d_in[2];
    const float* wv = (const float*)d_in[3];
    float* out = (float*)d_out;

    __half *xh, *wh, *Qh, *Kh, *VhT, *Eh;
    cudaGetSymbolAddress((void**)&xh, g_xh);
    cudaGetSymbolAddress((void**)&wh, g_wh);
    cudaGetSymbolAddress((void**)&Qh, g_Qh);
    cudaGetSymbolAddress((void**)&Kh, g_Kh);
    cudaGetSymbolAddress((void**)&VhT, g_VhT);
    cudaGetSymbolAddress((void**)&Eh, g_Eh);

    cudaFuncSetAttribute(mma_gemm_kernel<1>, cudaFuncAttributeMaxDynamicSharedMemorySize, GSMEM);
    cudaFuncSetAttribute(mma_gemm_kernel<2>, cudaFuncAttributeMaxDynamicSharedMemorySize, GSMEM);
    cudaFuncSetAttribute(mma_gemm_kernel<3>, cudaFuncAttributeMaxDynamicSharedMemorySize, GSMEM);

    // 0: prep (tables + cvt_x + cvt_w)
    prep_kernel<<<23552, 256>>>(x, wq, wk, wv);

    // 1: Merged QKV projection (persistent, 24x128 tiles, K=1024)
    mma_gemm_kernel<1><<<296, 128, GSMEM>>>(xh, wh, nullptr, DD, 0,
                                            0, 0, 0, 1.0f,
                                            24, 24 * 128, 3072);

    // 2: scores -> exp fp16 + psum (persistent, 16x16x8 tiles, K=1024)
    mma_gemm_kernel<2><<<296, 128, GSMEM>>>(Qh, Kh, nullptr, DD, 0,
                                            (long)MM * DD, (long)MM * DD, 0,
                                            0.03125f,
                                            16, 16 * 16, 2048);

    // 3: out = exp(S) @ V / rowsum (persistent, 8x16x8 tiles, K=2048)
    mma_gemm_kernel<3><<<296, 128, GSMEM>>>(Eh, VhT, out, MM, DD,
                                            (long)MM * MM, (long)DD * MM,
                                            (long)MM * DD, 1.0f,
                                            8, 8 * 16, 1024);
}